// round 1
// baseline (speedup 1.0000x reference)
#include <cuda_runtime.h>

#define N_NODES 50000
#define N_EDGES 800000
#define IN_F    512
#define F       256     // HEADS*HID
#define EDGE_F  32
#define CHK_E   16      // edges per shared chunk in fused kernel

typedef unsigned long long ull;

// ---------------- scratch (device globals; no allocations allowed) ----------
__device__ int   g_is64;
__device__ int   g_src[N_EDGES];
__device__ int   g_dst[N_EDGES];
__device__ int   g_deg[N_NODES];
__device__ int   g_rowptr[N_NODES + 1];
__device__ int   g_cursor[N_NODES];
__device__ int   g_eidx[N_EDGES];
__device__ float g_xl[(size_t)N_NODES * F];
__device__ float g_xr[(size_t)N_NODES * F];
__device__ float g_h [(size_t)N_NODES * F];

// ---------------- packed fp32x2 helpers (B300 FFMA2 path) -------------------
__device__ __forceinline__ ull pack2(float x, float y) {
    ull r; asm("mov.b64 %0, {%1, %2};" : "=l"(r) : "f"(x), "f"(y)); return r;
}
__device__ __forceinline__ void unpack2(ull v, float& x, float& y) {
    asm("mov.b64 {%0, %1}, %2;" : "=f"(x), "=f"(y) : "l"(v));
}
__device__ __forceinline__ ull fma2(ull a, ull b, ull c) {
    ull d; asm("fma.rn.f32x2 %0, %1, %2, %3;" : "=l"(d) : "l"(a), "l"(b), "l"(c));
    return d;
}

// ---------------- edge_index dtype detection + CSR build --------------------
__global__ void k_detect(const int* ei32) {
    if (threadIdx.x == 0) {
        // int64 values < 50000 -> every odd 32-bit word is 0.
        int is64 = 1;
        for (int i = 0; i < 32; i++) {
            if (ei32[2 * i + 1] != 0) { is64 = 0; break; }
        }
        g_is64 = is64;
    }
}

__global__ void k_prep(const void* ei) {
    const int is64 = g_is64;
    const int*       ei32 = (const int*)ei;
    const long long* ei64 = (const long long*)ei;
    int stride = gridDim.x * blockDim.x;
    for (int e = blockIdx.x * blockDim.x + threadIdx.x; e < N_EDGES; e += stride) {
        int s, d;
        if (is64) { s = (int)ei64[e]; d = (int)ei64[N_EDGES + e]; }
        else      { s = ei32[e];      d = ei32[N_EDGES + e]; }
        // safety clamp (wrong only if detection wrong; avoids OOB crash)
        s = min(max(s, 0), N_NODES - 1);
        d = min(max(d, 0), N_NODES - 1);
        g_src[e] = s; g_dst[e] = d;
    }
    for (int i = blockIdx.x * blockDim.x + threadIdx.x; i < N_NODES; i += stride)
        g_deg[i] = 0;
}

__global__ void k_hist() {
    int stride = gridDim.x * blockDim.x;
    for (int e = blockIdx.x * blockDim.x + threadIdx.x; e < N_EDGES; e += stride)
        atomicAdd(&g_deg[g_dst[e]], 1);
}

__global__ void k_scan() {   // single block of 1024 threads
    __shared__ int sums[1024];
    const int CH = (N_NODES + 1023) / 1024;
    int t = threadIdx.x;
    int start = t * CH;
    int end   = min(start + CH, N_NODES);
    int s = 0;
    for (int i = start; i < end; i++) s += g_deg[i];
    sums[t] = s;
    __syncthreads();
    // Hillis-Steele inclusive scan
    for (int off = 1; off < 1024; off <<= 1) {
        int v = (t >= off) ? sums[t - off] : 0;
        __syncthreads();
        sums[t] += v;
        __syncthreads();
    }
    int run = (t == 0) ? 0 : sums[t - 1];
    for (int i = start; i < end; i++) {
        g_rowptr[i] = run;
        g_cursor[i] = run;
        run += g_deg[i];
    }
    if (t == 1023) g_rowptr[N_NODES] = run;
}

__global__ void k_scatter() {
    int stride = gridDim.x * blockDim.x;
    for (int e = blockIdx.x * blockDim.x + threadIdx.x; e < N_EDGES; e += stride) {
        int p = atomicAdd(&g_cursor[g_dst[e]], 1);
        g_eidx[p] = e;
    }
}

// ---------------- node GEMM: [xl|xr] = A[N,K] @ [Wl|Wr] + [bl|br] -----------
// 128x128x16 tile, 256 threads, 8x8 per thread, FFMA2 microkernel.
// A == nullptr means "use g_h" (layer-1 input).
__global__ __launch_bounds__(256)
void k_gemm(const float* __restrict__ A_in, int K,
            const float* __restrict__ Wl, const float* __restrict__ Wr,
            const float* __restrict__ bl, const float* __restrict__ br)
{
    __shared__ float As[16][128];
    __shared__ float Bs[16][128];

    const float* A = A_in ? A_in : g_h;

    int bm = blockIdx.x * 128;
    int bn = blockIdx.y * 128;            // 0,128 -> Wl/xl ; 256,384 -> Wr/xr
    const float* W    = (bn < 256) ? Wl : Wr;
    const float* bias = (bn < 256) ? bl : br;
    float*       Cb   = (bn < 256) ? g_xl : g_xr;
    int cb = bn & 255;

    int tid  = threadIdx.x;
    int arow = tid >> 1, acol = (tid & 1) * 8;
    int bkr  = tid >> 4, bcc  = (tid & 15) * 8;
    int ty   = (tid >> 4) * 8, tx = (tid & 15) * 8;

    ull acc[8][4];
#pragma unroll
    for (int i = 0; i < 8; i++)
#pragma unroll
        for (int j = 0; j < 4; j++) acc[i][j] = 0ull;

    int  gr_a = bm + arow;
    bool aval = gr_a < N_NODES;
    const float* Arow = A + (size_t)gr_a * K;

    for (int k0 = 0; k0 < K; k0 += 16) {
        float4 a0 = make_float4(0.f, 0.f, 0.f, 0.f), a1 = a0;
        if (aval) {
            a0 = *(const float4*)&Arow[k0 + acol];
            a1 = *(const float4*)&Arow[k0 + acol + 4];
        }
        As[acol + 0][arow] = a0.x; As[acol + 1][arow] = a0.y;
        As[acol + 2][arow] = a0.z; As[acol + 3][arow] = a0.w;
        As[acol + 4][arow] = a1.x; As[acol + 5][arow] = a1.y;
        As[acol + 6][arow] = a1.z; As[acol + 7][arow] = a1.w;

        float4 b0 = *(const float4*)&W[(size_t)(k0 + bkr) * 256 + cb + bcc];
        float4 b1 = *(const float4*)&W[(size_t)(k0 + bkr) * 256 + cb + bcc + 4];
        *(float4*)&Bs[bkr][bcc]     = b0;
        *(float4*)&Bs[bkr][bcc + 4] = b1;
        __syncthreads();

#pragma unroll
        for (int kk = 0; kk < 16; kk++) {
            float a[8];
            *(float4*)&a[0] = *(const float4*)&As[kk][ty];
            *(float4*)&a[4] = *(const float4*)&As[kk][ty + 4];
            ull b[4];
            const ull* bp = (const ull*)&Bs[kk][tx];
            b[0] = bp[0]; b[1] = bp[1]; b[2] = bp[2]; b[3] = bp[3];
#pragma unroll
            for (int i = 0; i < 8; i++) {
                ull ap = pack2(a[i], a[i]);
#pragma unroll
                for (int j = 0; j < 4; j++) acc[i][j] = fma2(ap, b[j], acc[i][j]);
            }
        }
        __syncthreads();
    }

    float2 bias2[4];
#pragma unroll
    for (int j = 0; j < 4; j++) bias2[j] = *(const float2*)&bias[cb + tx + 2 * j];

#pragma unroll
    for (int i = 0; i < 8; i++) {
        int gr = bm + ty + i;
        if (gr < N_NODES) {
#pragma unroll
            for (int j = 0; j < 4; j++) {
                float vx, vy; unpack2(acc[i][j], vx, vy);
                float2 o = make_float2(vx + bias2[j].x, vy + bias2[j].y);
                *(float2*)&Cb[(size_t)gr * 256 + cb + tx + 2 * j] = o;
            }
        }
    }
}

// ---------------- fused GATv2 edge kernel (one block per dst node) ----------
// 128 threads: warp w = head w, lane covers channels (2t, 2t+1).
// Computes ea = edge_attr@We on the fly, logits, online softmax, aggregation,
// bias + relu. Writes h into g_h. No float atomics.
__global__ __launch_bounds__(128)
void k_gat_edge(const float* __restrict__ We,    // [32,256]
                const float* __restrict__ att,   // [4,64] = 256 flat
                const float* __restrict__ bias,  // [256]
                const float* __restrict__ eattr) // [E,32]
{
    int d = blockIdx.x;
    int t = threadIdx.x;          // 0..127
    int lane = t & 31;

    // W_e column pair in registers (32 packed pairs)
    ull we2[32];
#pragma unroll
    for (int k = 0; k < 32; k++) {
        float2 w = *(const float2*)&We[k * 256 + 2 * t];
        we2[k] = pack2(w.x, w.y);
    }
    float2 xr2  = *(const float2*)&g_xr[(size_t)d * 256 + 2 * t];
    float2 att2 = *(const float2*)&att[2 * t];

    int e0  = g_rowptr[d];
    int e1  = g_rowptr[d + 1];
    int deg = e1 - e0;

    __shared__ ull ea_s[CHK_E][32];   // edge_attr value duplicated into both halves
    __shared__ int src_s[CHK_E];

    float m_run = -1e30f, s_run = 0.f;
    float accx = 0.f, accy = 0.f;

    for (int base = 0; base < deg; base += CHK_E) {
        int cnt = min(CHK_E, deg - base);
        if (t < cnt) src_s[t] = g_src[g_eidx[e0 + base + t]];
        for (int j = (t >> 5); j < cnt; j += 4) {
            int eid = g_eidx[e0 + base + j];
            float v = eattr[(size_t)eid * 32 + lane];
            ea_s[j][lane] = pack2(v, v);
        }
        __syncthreads();

        for (int j = 0; j < cnt; j++) {
            int s = src_s[j];
            float2 xl2 = *(const float2*)&g_xl[(size_t)s * 256 + 2 * t];

            ull a0 = 0ull, a1 = 0ull;
#pragma unroll
            for (int k = 0; k < 32; k += 2) {
                a0 = fma2(ea_s[j][k],     we2[k],     a0);
                a1 = fma2(ea_s[j][k + 1], we2[k + 1], a1);
            }
            float f0x, f0y, f1x, f1y;
            unpack2(a0, f0x, f0y); unpack2(a1, f1x, f1y);

            float vx = xl2.x + xr2.x + f0x + f1x;
            float vy = xl2.y + xr2.y + f0y + f1y;
            vx = vx > 0.f ? vx : 0.2f * vx;   // leaky_relu(0.2)
            vy = vy > 0.f ? vy : 0.2f * vy;

            float p = vx * att2.x + vy * att2.y;
#pragma unroll
            for (int off = 16; off; off >>= 1)
                p += __shfl_xor_sync(0xffffffffu, p, off);

            float mnew  = fmaxf(m_run, p);
            float scale = __expf(m_run - mnew);
            float w     = __expf(p - mnew);
            s_run = s_run * scale + w;
            accx  = accx * scale + w * xl2.x;
            accy  = accy * scale + w * xl2.y;
            m_run = mnew;
        }
        __syncthreads();
    }

    float inv = (deg > 0) ? (1.f / s_run) : 0.f;
    float ox = accx * inv + bias[2 * t];
    float oy = accy * inv + bias[2 * t + 1];
    ox = fmaxf(ox, 0.f);
    oy = fmaxf(oy, 0.f);
    *(float2*)&g_h[(size_t)d * 256 + 2 * t] = make_float2(ox, oy);
}

// ---------------- output projection: y = h1 @ W_out + b_out -----------------
__global__ __launch_bounds__(256)
void k_out(const float* __restrict__ Wout, const float* __restrict__ bout,
           float* __restrict__ y)
{
    int warp = (blockIdx.x * blockDim.x + threadIdx.x) >> 5;
    int lane = threadIdx.x & 31;
    if (warp >= N_NODES) return;
    const float* h = &g_h[(size_t)warp * 256];
    float s = 0.f;
#pragma unroll
    for (int i = 0; i < 8; i++)
        s += h[lane + 32 * i] * Wout[lane + 32 * i];
#pragma unroll
    for (int off = 16; off; off >>= 1)
        s += __shfl_xor_sync(0xffffffffu, s, off);
    if (lane == 0) y[warp] = s + bout[0];
}

// ---------------- launch ----------------------------------------------------
extern "C" void kernel_launch(void* const* d_in, const int* in_sizes, int n_in,
                              void* d_out, int out_size)
{
    const float* x     = (const float*)d_in[0];
    const void*  ei    = d_in[1];
    const float* eattr = (const float*)d_in[2];
    const float* Wl0   = (const float*)d_in[3];
    const float* bl0   = (const float*)d_in[4];
    const float* Wr0   = (const float*)d_in[5];
    const float* br0   = (const float*)d_in[6];
    const float* We0   = (const float*)d_in[7];
    const float* att0  = (const float*)d_in[8];
    const float* bias0 = (const float*)d_in[9];
    const float* Wl1   = (const float*)d_in[10];
    const float* bl1   = (const float*)d_in[11];
    const float* Wr1   = (const float*)d_in[12];
    const float* br1   = (const float*)d_in[13];
    const float* We1   = (const float*)d_in[14];
    const float* att1  = (const float*)d_in[15];
    const float* bias1 = (const float*)d_in[16];
    const float* Wout  = (const float*)d_in[17];
    const float* bout  = (const float*)d_in[18];
    float* y = (float*)d_out;

    // CSR build (once; shared by both layers)
    k_detect <<<1, 32>>>((const int*)ei);
    k_prep   <<<512, 256>>>(ei);
    k_hist   <<<512, 256>>>();
    k_scan   <<<1, 1024>>>();
    k_scatter<<<512, 256>>>();

    dim3 gg((N_NODES + 127) / 128, 4);

    // layer 0
    k_gemm<<<gg, 256>>>(x, IN_F, Wl0, Wr0, bl0, br0);
    k_gat_edge<<<N_NODES, 128>>>(We0, att0, bias0, eattr);

    // layer 1 (input = g_h, signalled by nullptr)
    k_gemm<<<gg, 256>>>(nullptr, F, Wl1, Wr1, bl1, br1);
    k_gat_edge<<<N_NODES, 128>>>(We1, att1, bias1, eattr);

    // output projection
    k_out<<<(N_NODES * 32 + 255) / 256, 256>>>(Wout, bout, y);
}

// round 3
// speedup vs baseline: 1.1473x; 1.1473x over previous
#include <cuda_runtime.h>
#include <cuda_bf16.h>
#include <cstdint>

#define N_NODES 50000
#define N_EDGES 800000
#define IN_F    512
#define F       256
#define CHK_E   16

#define MT 128
#define NT 128
#define KC 32                  // bf16 elems per k-chunk
#define M_TILES 391            // ceil(50000/128)
#define M_PAD   (M_TILES*128)  // 50048
#define APAD    40             // smem row stride (elems) for conflict-free ldmatrix

typedef unsigned long long ull;

// ---------------- scratch (device globals) -----------------------------------
__device__ int   g_is64;
__device__ int   g_src[N_EDGES];
__device__ int   g_dst[N_EDGES];
__device__ int   g_deg[N_NODES];
__device__ int   g_rowptr[N_NODES + 1];
__device__ int   g_cursor[N_NODES];
__device__ int   g_eidx[N_EDGES];
__device__ float g_xl[(size_t)N_NODES * F];
__device__ float g_xr[(size_t)N_NODES * F];
__device__ float g_h [(size_t)N_NODES * F];
__device__ __nv_bfloat16 g_abf[(size_t)M_PAD * 1024];   // A'' = [hi|lo], K<=512
__device__ __nv_bfloat16 g_bbf[(size_t)512 * 1536];     // B'' = [hi|hi|lo]
#define SCAN_T 2048
__device__ int   g_tsum[SCAN_T];

// ---------------- fp32x2 helpers ----------------------------------------------
__device__ __forceinline__ ull pack2(float x, float y) {
    ull r; asm("mov.b64 %0, {%1, %2};" : "=l"(r) : "f"(x), "f"(y)); return r;
}
__device__ __forceinline__ void unpack2(ull v, float& x, float& y) {
    asm("mov.b64 {%0, %1}, %2;" : "=f"(x), "=f"(y) : "l"(v));
}
__device__ __forceinline__ ull fma2(ull a, ull b, ull c) {
    ull d; asm("fma.rn.f32x2 %0, %1, %2, %3;" : "=l"(d) : "l"(a), "l"(b), "l"(c));
    return d;
}

// ---------------- mma / ldmatrix / cp.async helpers -----------------------------
__device__ __forceinline__ uint32_t smem_u32(const void* p) {
    uint32_t a;
    asm("{ .reg .u64 t; cvta.to.shared.u64 t, %1; cvt.u32.u64 %0, t; }"
        : "=r"(a) : "l"(p));
    return a;
}
__device__ __forceinline__ void cp16(uint32_t dst, const void* src) {
    asm volatile("cp.async.cg.shared.global [%0], [%1], 16;" :: "r"(dst), "l"(src));
}
#define CP_COMMIT() asm volatile("cp.async.commit_group;" ::: "memory")
#define CP_WAIT(n)  asm volatile("cp.async.wait_group %0;" :: "n"(n) : "memory")

__device__ __forceinline__ void ldmx4(uint32_t* r, uint32_t addr) {
    asm volatile("ldmatrix.sync.aligned.m8n8.x4.shared.b16 {%0,%1,%2,%3}, [%4];"
                 : "=r"(r[0]), "=r"(r[1]), "=r"(r[2]), "=r"(r[3]) : "r"(addr));
}
__device__ __forceinline__ void mma_bf16(float* c, const uint32_t* a, uint32_t b0, uint32_t b1) {
    asm volatile(
        "mma.sync.aligned.m16n8k16.row.col.f32.bf16.bf16.f32 "
        "{%0,%1,%2,%3}, {%4,%5,%6,%7}, {%8,%9}, {%0,%1,%2,%3};"
        : "+f"(c[0]), "+f"(c[1]), "+f"(c[2]), "+f"(c[3])
        : "r"(a[0]), "r"(a[1]), "r"(a[2]), "r"(a[3]), "r"(b0), "r"(b1));
}

// ---------------- edge_index dtype detection + CSR build ------------------------
__global__ void k_detect(const int* ei32) {
    if (threadIdx.x == 0) {
        int is64 = 1;
        for (int i = 0; i < 32; i++)
            if (ei32[2 * i + 1] != 0) { is64 = 0; break; }
        g_is64 = is64;
    }
}
__global__ void k_prep(const void* ei) {
    const int is64 = g_is64;
    const int*       ei32 = (const int*)ei;
    const long long* ei64 = (const long long*)ei;
    int stride = gridDim.x * blockDim.x;
    for (int e = blockIdx.x * blockDim.x + threadIdx.x; e < N_EDGES; e += stride) {
        int s, d;
        if (is64) { s = (int)ei64[e]; d = (int)ei64[N_EDGES + e]; }
        else      { s = ei32[e];      d = ei32[N_EDGES + e]; }
        s = min(max(s, 0), N_NODES - 1);
        d = min(max(d, 0), N_NODES - 1);
        g_src[e] = s; g_dst[e] = d;
    }
    for (int i = blockIdx.x * blockDim.x + threadIdx.x; i < N_NODES; i += stride)
        g_deg[i] = 0;
}
__global__ void k_hist() {
    int stride = gridDim.x * blockDim.x;
    for (int e = blockIdx.x * blockDim.x + threadIdx.x; e < N_EDGES; e += stride)
        atomicAdd(&g_deg[g_dst[e]], 1);
}
__global__ void k_scanA() {
    int t = blockIdx.x * blockDim.x + threadIdx.x;
    int st = t * 25, en = min(st + 25, N_NODES);
    int s = 0;
    for (int i = st; i < en; i++) s += g_deg[i];
    g_tsum[t] = s;
}
__global__ void k_scanB() {
    __shared__ int sh[256];
    int t = threadIdx.x;
    int v[8]; int s = 0;
#pragma unroll
    for (int j = 0; j < 8; j++) v[j] = g_tsum[t * 8 + j];
#pragma unroll
    for (int j = 0; j < 8; j++) { int tmp = v[j]; v[j] = s; s += tmp; }
    sh[t] = s;
    __syncthreads();
    for (int off = 1; off < 256; off <<= 1) {
        int x = (t >= off) ? sh[t - off] : 0;
        __syncthreads();
        sh[t] += x;
        __syncthreads();
    }
    int base = (t == 0) ? 0 : sh[t - 1];
#pragma unroll
    for (int j = 0; j < 8; j++) g_tsum[t * 8 + j] = base + v[j];
}
__global__ void k_scanC() {
    int t = blockIdx.x * blockDim.x + threadIdx.x;
    int st = t * 25, en = min(st + 25, N_NODES);
    int run = g_tsum[t];
    for (int i = st; i < en; i++) {
        g_rowptr[i] = run;
        g_cursor[i] = run;
        run += g_deg[i];
    }
    if (t == 0) g_rowptr[N_NODES] = N_EDGES;
}
__global__ void k_scatter() {
    int stride = gridDim.x * blockDim.x;
    for (int e = blockIdx.x * blockDim.x + threadIdx.x; e < N_EDGES; e += stride) {
        int p = atomicAdd(&g_cursor[g_dst[e]], 1);
        g_eidx[p] = e;
    }
}

// ---------------- bf16 split conversions ----------------------------------------
__global__ void k_cvt_a(const float* A_in, int K, int kshift) {
    const float* A = A_in ? A_in : g_h;
    size_t total = (size_t)N_NODES * K;
    size_t stride = (size_t)gridDim.x * blockDim.x;
    for (size_t i = blockIdx.x * (size_t)blockDim.x + threadIdx.x; i < total; i += stride) {
        size_t row = i >> kshift;
        int k = (int)(i & (K - 1));
        float a = A[i];
        __nv_bfloat16 hi = __float2bfloat16(a);
        __nv_bfloat16 lo = __float2bfloat16(a - __bfloat162float(hi));
        size_t base = row * (size_t)(2 * K);
        g_abf[base + k]     = hi;
        g_abf[base + K + k] = lo;
    }
}
__global__ void k_cvt_w(const float* Wl, const float* Wr, int K, int kshift) {
    int KK = 3 * K;
    int total = 512 * K;
    int stride = gridDim.x * blockDim.x;
    for (int i = blockIdx.x * blockDim.x + threadIdx.x; i < total; i += stride) {
        int n = i >> kshift;
        int k = i & (K - 1);
        float w = (n < 256) ? Wl[(size_t)k * 256 + n] : Wr[(size_t)k * 256 + (n - 256)];
        __nv_bfloat16 hi = __float2bfloat16(w);
        __nv_bfloat16 lo = __float2bfloat16(w - __bfloat162float(hi));
        size_t base = (size_t)n * KK;
        g_bbf[base + k]         = hi;
        g_bbf[base + K + k]     = hi;
        g_bbf[base + 2 * K + k] = lo;
    }
}

// ---------------- mma.sync GEMM: [xl|xr] = A''@B''^T + bias ----------------------
// CTA 128x128, 8 warps (2m x 4n), warp tile 64x32, cp.async double buffer.
__global__ __launch_bounds__(256)
void k_mma(int KA /*2K*/, int KK /*3K*/,
           const float* __restrict__ bl, const float* __restrict__ br)
{
    __shared__ __align__(128) __nv_bfloat16 smA[2][128 * APAD];
    __shared__ __align__(128) __nv_bfloat16 smB[2][128 * APAD];

    const int tid  = threadIdx.x;
    const int wid  = tid >> 5, lane = tid & 31;
    const int wm   = (wid & 1) * 64;       // warp m offset
    const int wn   = (wid >> 1) * 32;      // warp n offset
    const int bm   = blockIdx.x, bn = blockIdx.y;

    const __nv_bfloat16* Abase = g_abf + (size_t)bm * MT * KA;
    const __nv_bfloat16* Bbase = g_bbf + (size_t)bn * NT * KK;

    const int nchunks = KK / KC;
    const int n2      = KA / KC;

    // per-thread cp.async src/dst positions (2 x 16B per tile per thread)
    const int r0 = tid >> 1, s0 = (tid & 1) * 2;       // units: (row, 2 segs of 8 elems)
    uint32_t aS[2], bS[2];
    aS[0] = smem_u32(&smA[0][0]); aS[1] = smem_u32(&smA[1][0]);
    bS[0] = smem_u32(&smB[0][0]); bS[1] = smem_u32(&smB[1][0]);

    // ldmatrix lane addresses (byte offsets within a buffer)
    const uint32_t aOff = (uint32_t)(((wm + (lane & 15)) * APAD + (lane >> 4) * 8) * 2);
    const uint32_t bOff = (uint32_t)(((wn + (lane & 7) + ((lane >> 4) & 1) * 8) * APAD
                                      + ((lane >> 3) & 1) * 8) * 2);

    float acc[4][4][4];
#pragma unroll
    for (int i = 0; i < 4; i++)
#pragma unroll
        for (int j = 0; j < 4; j++)
#pragma unroll
            for (int q = 0; q < 4; q++) acc[i][j][q] = 0.f;

    auto load_chunk = [&](int c, int buf) {
        int ak0 = ((c < n2) ? c : (c - n2)) * KC;
        int bk0 = c * KC;
#pragma unroll
        for (int i = 0; i < 2; i++) {
            int r = r0 + i * 128 / 1;      // two rows? no: two segs
            (void)r;
        }
        // each thread: row r0 (0..127), segments s0 and s0+1 (of 4 8-elem segs)
#pragma unroll
        for (int i = 0; i < 2; i++) {
            int s = s0 + i;
            cp16(aS[buf] + (uint32_t)((r0 * APAD + s * 8) * 2),
                 Abase + (size_t)r0 * KA + ak0 + s * 8);
            cp16(bS[buf] + (uint32_t)((r0 * APAD + s * 8) * 2),
                 Bbase + (size_t)r0 * KK + bk0 + s * 8);
        }
        CP_COMMIT();
    };

    load_chunk(0, 0);

    for (int c = 0; c < nchunks; c++) {
        int buf = c & 1;
        if (c + 1 < nchunks) {
            load_chunk(c + 1, buf ^ 1);
            CP_WAIT(1);
        } else {
            CP_WAIT(0);
        }
        __syncthreads();

#pragma unroll
        for (int ks = 0; ks < 2; ks++) {
            uint32_t afr[4][4];
#pragma unroll
            for (int mi = 0; mi < 4; mi++)
                ldmx4(afr[mi], aS[buf] + aOff + (uint32_t)(mi * 16 * APAD * 2 + ks * 32));
            uint32_t bfr[2][4];
#pragma unroll
            for (int g = 0; g < 2; g++)
                ldmx4(bfr[g], bS[buf] + bOff + (uint32_t)(g * 16 * APAD * 2 + ks * 32));
#pragma unroll
            for (int mi = 0; mi < 4; mi++)
#pragma unroll
                for (int ni = 0; ni < 4; ni++)
                    mma_bf16(acc[mi][ni], afr[mi], bfr[ni >> 1][(ni & 1) * 2],
                             bfr[ni >> 1][(ni & 1) * 2 + 1]);
        }
        __syncthreads();
    }

    // epilogue
    const float* bias = (bn < 2) ? bl : br;
    float*       Cout = (bn < 2) ? g_xl : g_xr;
    const int cbase = (bn & 1) * 128;
#pragma unroll
    for (int mi = 0; mi < 4; mi++) {
        int mrow = bm * MT + wm + mi * 16 + (lane >> 2);
#pragma unroll
        for (int ni = 0; ni < 4; ni++) {
            int col = cbase + wn + ni * 8 + (lane & 3) * 2;
            float b0 = bias[col], b1 = bias[col + 1];
            if (mrow < N_NODES) {
                float2 o = make_float2(acc[mi][ni][0] + b0, acc[mi][ni][1] + b1);
                *(float2*)&Cout[(size_t)mrow * 256 + col] = o;
            }
            if (mrow + 8 < N_NODES) {
                float2 o = make_float2(acc[mi][ni][2] + b0, acc[mi][ni][3] + b1);
                *(float2*)&Cout[(size_t)(mrow + 8) * 256 + col] = o;
            }
        }
    }
}

// ---------------- fused GATv2 edge kernel (one block per dst node) ---------------
__global__ __launch_bounds__(128)
void k_gat_edge(const float* __restrict__ We,
                const float* __restrict__ att,
                const float* __restrict__ bias,
                const float* __restrict__ eattr)
{
    int d = blockIdx.x;
    int t = threadIdx.x;
    int lane = t & 31;

    ull we2[32];
#pragma unroll
    for (int k = 0; k < 32; k++) {
        float2 w = *(const float2*)&We[k * 256 + 2 * t];
        we2[k] = pack2(w.x, w.y);
    }
    float2 xr2  = *(const float2*)&g_xr[(size_t)d * 256 + 2 * t];
    float2 att2 = *(const float2*)&att[2 * t];

    int e0  = g_rowptr[d];
    int e1  = g_rowptr[d + 1];
    int deg = e1 - e0;

    __shared__ ull ea_s[CHK_E][32];
    __shared__ int src_s[CHK_E];

    float m_run = -1e30f, s_run = 0.f;
    float accx = 0.f, accy = 0.f;

    for (int base = 0; base < deg; base += CHK_E) {
        int cnt = min(CHK_E, deg - base);
        if (t < cnt) src_s[t] = g_src[g_eidx[e0 + base + t]];
        for (int j = (t >> 5); j < cnt; j += 4) {
            int eid = g_eidx[e0 + base + j];
            float v = eattr[(size_t)eid * 32 + lane];
            ea_s[j][lane] = pack2(v, v);
        }
        __syncthreads();

        for (int j = 0; j < cnt; j++) {
            int s = src_s[j];
            float2 xl2 = *(const float2*)&g_xl[(size_t)s * 256 + 2 * t];

            ull a0 = 0ull, a1 = 0ull;
#pragma unroll
            for (int k = 0; k < 32; k += 2) {
                a0 = fma2(ea_s[j][k],     we2[k],     a0);
                a1 = fma2(ea_s[j][k + 1], we2[k + 1], a1);
            }
            float f0x, f0y, f1x, f1y;
            unpack2(a0, f0x, f0y); unpack2(a1, f1x, f1y);

            float vx = xl2.x + xr2.x + f0x + f1x;
            float vy = xl2.y + xr2.y + f0y + f1y;
            vx = vx > 0.f ? vx : 0.2f * vx;
            vy = vy > 0.f ? vy : 0.2f * vy;

            float p = vx * att2.x + vy * att2.y;
#pragma unroll
            for (int off = 16; off; off >>= 1)
                p += __shfl_xor_sync(0xffffffffu, p, off);

            float mnew  = fmaxf(m_run, p);
            float scale = __expf(m_run - mnew);
            float w     = __expf(p - mnew);
            s_run = s_run * scale + w;
            accx  = accx * scale + w * xl2.x;
            accy  = accy * scale + w * xl2.y;
            m_run = mnew;
        }
        __syncthreads();
    }

    float inv = (deg > 0) ? (1.f / s_run) : 0.f;
    float ox = accx * inv + bias[2 * t];
    float oy = accy * inv + bias[2 * t + 1];
    ox = fmaxf(ox, 0.f);
    oy = fmaxf(oy, 0.f);
    *(float2*)&g_h[(size_t)d * 256 + 2 * t] = make_float2(ox, oy);
}

// ---------------- output projection ------------------------------------------------
__global__ __launch_bounds__(256)
void k_out(const float* __restrict__ Wout, const float* __restrict__ bout,
           float* __restrict__ y)
{
    int warp = (blockIdx.x * blockDim.x + threadIdx.x) >> 5;
    int lane = threadIdx.x & 31;
    if (warp >= N_NODES) return;
    const float* h = &g_h[(size_t)warp * 256];
    float s = 0.f;
#pragma unroll
    for (int i = 0; i < 8; i++)
        s += h[lane + 32 * i] * Wout[lane + 32 * i];
#pragma unroll
    for (int off = 16; off; off >>= 1)
        s += __shfl_xor_sync(0xffffffffu, s, off);
    if (lane == 0) y[warp] = s + bout[0];
}

// ---------------- launch -------------------------------------------------------------
extern "C" void kernel_launch(void* const* d_in, const int* in_sizes, int n_in,
                              void* d_out, int out_size)
{
    const float* x     = (const float*)d_in[0];
    const void*  ei    = d_in[1];
    const float* eattr = (const float*)d_in[2];
    const float* Wl0   = (const float*)d_in[3];
    const float* bl0   = (const float*)d_in[4];
    const float* Wr0   = (const float*)d_in[5];
    const float* br0   = (const float*)d_in[6];
    const float* We0   = (const float*)d_in[7];
    const float* att0  = (const float*)d_in[8];
    const float* bias0 = (const float*)d_in[9];
    const float* Wl1   = (const float*)d_in[10];
    const float* bl1   = (const float*)d_in[11];
    const float* Wr1   = (const float*)d_in[12];
    const float* br1   = (const float*)d_in[13];
    const float* We1   = (const float*)d_in[14];
    const float* att1  = (const float*)d_in[15];
    const float* bias1 = (const float*)d_in[16];
    const float* Wout  = (const float*)d_in[17];
    const float* bout  = (const float*)d_in[18];
    float* y = (float*)d_out;

    // CSR build
    k_detect <<<1, 32>>>((const int*)ei);
    k_prep   <<<512, 256>>>(ei);
    k_hist   <<<512, 256>>>();
    k_scanA  <<<8, 256>>>();
    k_scanB  <<<1, 256>>>();
    k_scanC  <<<8, 256>>>();
    k_scatter<<<512, 256>>>();

    dim3 gmma(M_TILES, 4);

    // layer 0
    k_cvt_w<<<64, 256>>>(Wl0, Wr0, 512, 9);
    k_cvt_a<<<512, 256>>>(x, 512, 9);
    k_mma<<<gmma, 256>>>(1024, 1536, bl0, br0);
    k_gat_edge<<<N_NODES, 128>>>(We0, att0, bias0, eattr);

    // layer 1
    k_cvt_w<<<64, 256>>>(Wl1, Wr1, 256, 8);
    k_cvt_a<<<512, 256>>>(nullptr, 256, 8);
    k_mma<<<gmma, 256>>>(512, 768, bl1, br1);
    k_gat_edge<<<N_NODES, 128>>>(We1, att1, bias1, eattr);

    // output projection
    k_out<<<(N_NODES * 32 + 255) / 256, 256>>>(Wout, bout, y);
}

// round 4
// speedup vs baseline: 1.4684x; 1.2799x over previous
#include <cuda_runtime.h>
#include <cuda_bf16.h>
#include <cstdint>

#define N_NODES 50000
#define N_EDGES 800000
#define IN_F    512
#define F       256
#define CHK_E   32

#define MT 128
#define NT 128
#define KC 32                  // bf16 elems per k-chunk
#define M_TILES 391            // ceil(50000/128)
#define M_PAD   (M_TILES*128)  // 50048
#define APAD    40             // smem row stride (elems) for conflict-free ldmatrix

typedef unsigned long long ull;

// ---------------- scratch (device globals) -----------------------------------
__device__ int   g_is64;
__device__ int   g_src[N_EDGES];
__device__ int   g_dst[N_EDGES];
__device__ int   g_deg[N_NODES];
__device__ int   g_rowptr[N_NODES + 1];
__device__ int   g_cursor[N_NODES];
__device__ int   g_eidx[N_EDGES];
__device__ int   g_srcs[N_EDGES];          // src gathered into CSR order
__device__ float g_xl[(size_t)N_NODES * F];
__device__ float g_xr[(size_t)N_NODES * F];
__device__ float g_h [(size_t)N_NODES * F];
__device__ __nv_bfloat16 g_abf[(size_t)M_PAD * 1024];   // A'' = [hi|lo], K<=512
__device__ __nv_bfloat16 g_bbf[(size_t)512 * 1536];     // B'' = [hi|hi|lo]
#define SCAN_T 2048
__device__ int   g_tsum[SCAN_T];

// ---------------- fp32x2 helpers ----------------------------------------------
__device__ __forceinline__ ull pack2(float x, float y) {
    ull r; asm("mov.b64 %0, {%1, %2};" : "=l"(r) : "f"(x), "f"(y)); return r;
}
__device__ __forceinline__ void unpack2(ull v, float& x, float& y) {
    asm("mov.b64 {%0, %1}, %2;" : "=f"(x), "=f"(y) : "l"(v));
}
__device__ __forceinline__ ull fma2(ull a, ull b, ull c) {
    ull d; asm("fma.rn.f32x2 %0, %1, %2, %3;" : "=l"(d) : "l"(a), "l"(b), "l"(c));
    return d;
}

// ---------------- mma / ldmatrix / cp.async helpers -----------------------------
__device__ __forceinline__ uint32_t smem_u32(const void* p) {
    uint32_t a;
    asm("{ .reg .u64 t; cvta.to.shared.u64 t, %1; cvt.u32.u64 %0, t; }"
        : "=r"(a) : "l"(p));
    return a;
}
__device__ __forceinline__ void cp16(uint32_t dst, const void* src) {
    asm volatile("cp.async.cg.shared.global [%0], [%1], 16;" :: "r"(dst), "l"(src));
}
#define CP_COMMIT() asm volatile("cp.async.commit_group;" ::: "memory")
#define CP_WAIT(n)  asm volatile("cp.async.wait_group %0;" :: "n"(n) : "memory")

__device__ __forceinline__ void ldmx4(uint32_t* r, uint32_t addr) {
    asm volatile("ldmatrix.sync.aligned.m8n8.x4.shared.b16 {%0,%1,%2,%3}, [%4];"
                 : "=r"(r[0]), "=r"(r[1]), "=r"(r[2]), "=r"(r[3]) : "r"(addr));
}
__device__ __forceinline__ void mma_bf16(float* c, const uint32_t* a, uint32_t b0, uint32_t b1) {
    asm volatile(
        "mma.sync.aligned.m16n8k16.row.col.f32.bf16.bf16.f32 "
        "{%0,%1,%2,%3}, {%4,%5,%6,%7}, {%8,%9}, {%0,%1,%2,%3};"
        : "+f"(c[0]), "+f"(c[1]), "+f"(c[2]), "+f"(c[3])
        : "r"(a[0]), "r"(a[1]), "r"(a[2]), "r"(a[3]), "r"(b0), "r"(b1));
}

// ---------------- edge_index dtype detection + CSR build ------------------------
__global__ void k_detect(const int* ei32) {
    if (threadIdx.x == 0) {
        int is64 = 1;
        for (int i = 0; i < 32; i++)
            if (ei32[2 * i + 1] != 0) { is64 = 0; break; }
        g_is64 = is64;
    }
}
__global__ void k_prep(const void* ei) {
    const int is64 = g_is64;
    const int*       ei32 = (const int*)ei;
    const long long* ei64 = (const long long*)ei;
    int stride = gridDim.x * blockDim.x;
    for (int e = blockIdx.x * blockDim.x + threadIdx.x; e < N_EDGES; e += stride) {
        int s, d;
        if (is64) { s = (int)ei64[e]; d = (int)ei64[N_EDGES + e]; }
        else      { s = ei32[e];      d = ei32[N_EDGES + e]; }
        s = min(max(s, 0), N_NODES - 1);
        d = min(max(d, 0), N_NODES - 1);
        g_src[e] = s; g_dst[e] = d;
    }
    for (int i = blockIdx.x * blockDim.x + threadIdx.x; i < N_NODES; i += stride)
        g_deg[i] = 0;
}
__global__ void k_hist() {
    int stride = gridDim.x * blockDim.x;
    for (int e = blockIdx.x * blockDim.x + threadIdx.x; e < N_EDGES; e += stride)
        atomicAdd(&g_deg[g_dst[e]], 1);
}
__global__ void k_scanA() {
    int t = blockIdx.x * blockDim.x + threadIdx.x;
    int st = t * 25, en = min(st + 25, N_NODES);
    int s = 0;
    for (int i = st; i < en; i++) s += g_deg[i];
    g_tsum[t] = s;
}
__global__ void k_scanB() {
    __shared__ int sh[256];
    int t = threadIdx.x;
    int v[8]; int s = 0;
#pragma unroll
    for (int j = 0; j < 8; j++) v[j] = g_tsum[t * 8 + j];
#pragma unroll
    for (int j = 0; j < 8; j++) { int tmp = v[j]; v[j] = s; s += tmp; }
    sh[t] = s;
    __syncthreads();
    for (int off = 1; off < 256; off <<= 1) {
        int x = (t >= off) ? sh[t - off] : 0;
        __syncthreads();
        sh[t] += x;
        __syncthreads();
    }
    int base = (t == 0) ? 0 : sh[t - 1];
#pragma unroll
    for (int j = 0; j < 8; j++) g_tsum[t * 8 + j] = base + v[j];
}
__global__ void k_scanC() {
    int t = blockIdx.x * blockDim.x + threadIdx.x;
    int st = t * 25, en = min(st + 25, N_NODES);
    int run = g_tsum[t];
    for (int i = st; i < en; i++) {
        g_rowptr[i] = run;
        g_cursor[i] = run;
        run += g_deg[i];
    }
    if (t == 0) g_rowptr[N_NODES] = N_EDGES;
}
__global__ void k_scatter() {
    int stride = gridDim.x * blockDim.x;
    for (int e = blockIdx.x * blockDim.x + threadIdx.x; e < N_EDGES; e += stride) {
        int s = g_src[e];
        int p = atomicAdd(&g_cursor[g_dst[e]], 1);
        g_eidx[p] = e;
        g_srcs[p] = s;
    }
}

// ---------------- bf16 split conversions ----------------------------------------
__global__ void k_cvt_a(const float* A_in, int K, int kshift) {
    const float* A = A_in ? A_in : g_h;
    size_t total = (size_t)N_NODES * K;
    size_t stride = (size_t)gridDim.x * blockDim.x;
    for (size_t i = blockIdx.x * (size_t)blockDim.x + threadIdx.x; i < total; i += stride) {
        size_t row = i >> kshift;
        int k = (int)(i & (K - 1));
        float a = A[i];
        __nv_bfloat16 hi = __float2bfloat16(a);
        __nv_bfloat16 lo = __float2bfloat16(a - __bfloat162float(hi));
        size_t base = row * (size_t)(2 * K);
        g_abf[base + k]     = hi;
        g_abf[base + K + k] = lo;
    }
}
__global__ void k_cvt_w(const float* Wl, const float* Wr, int K, int kshift) {
    int KK = 3 * K;
    int total = 512 * K;
    int stride = gridDim.x * blockDim.x;
    for (int i = blockIdx.x * blockDim.x + threadIdx.x; i < total; i += stride) {
        int n = i >> kshift;
        int k = i & (K - 1);
        float w = (n < 256) ? Wl[(size_t)k * 256 + n] : Wr[(size_t)k * 256 + (n - 256)];
        __nv_bfloat16 hi = __float2bfloat16(w);
        __nv_bfloat16 lo = __float2bfloat16(w - __bfloat162float(hi));
        size_t base = (size_t)n * KK;
        g_bbf[base + k]         = hi;
        g_bbf[base + K + k]     = hi;
        g_bbf[base + 2 * K + k] = lo;
    }
}

// ---------------- mma.sync GEMM: [xl|xr] = A''@B''^T + bias ----------------------
__global__ __launch_bounds__(256)
void k_mma(int KA /*2K*/, int KK /*3K*/,
           const float* __restrict__ bl, const float* __restrict__ br)
{
    __shared__ __align__(128) __nv_bfloat16 smA[2][128 * APAD];
    __shared__ __align__(128) __nv_bfloat16 smB[2][128 * APAD];

    const int tid  = threadIdx.x;
    const int wid  = tid >> 5, lane = tid & 31;
    const int wm   = (wid & 1) * 64;
    const int wn   = (wid >> 1) * 32;
    const int bm   = blockIdx.x, bn = blockIdx.y;

    const __nv_bfloat16* Abase = g_abf + (size_t)bm * MT * KA;
    const __nv_bfloat16* Bbase = g_bbf + (size_t)bn * NT * KK;

    const int nchunks = KK / KC;
    const int n2      = KA / KC;

    const int r0 = tid >> 1, s0 = (tid & 1) * 2;
    uint32_t aS[2], bS[2];
    aS[0] = smem_u32(&smA[0][0]); aS[1] = smem_u32(&smA[1][0]);
    bS[0] = smem_u32(&smB[0][0]); bS[1] = smem_u32(&smB[1][0]);

    const uint32_t aOff = (uint32_t)(((wm + (lane & 15)) * APAD + (lane >> 4) * 8) * 2);
    const uint32_t bOff = (uint32_t)(((wn + (lane & 7) + ((lane >> 4) & 1) * 8) * APAD
                                      + ((lane >> 3) & 1) * 8) * 2);

    float acc[4][4][4];
#pragma unroll
    for (int i = 0; i < 4; i++)
#pragma unroll
        for (int j = 0; j < 4; j++)
#pragma unroll
            for (int q = 0; q < 4; q++) acc[i][j][q] = 0.f;

    auto load_chunk = [&](int c, int buf) {
        int ak0 = ((c < n2) ? c : (c - n2)) * KC;
        int bk0 = c * KC;
#pragma unroll
        for (int i = 0; i < 2; i++) {
            int s = s0 + i;
            cp16(aS[buf] + (uint32_t)((r0 * APAD + s * 8) * 2),
                 Abase + (size_t)r0 * KA + ak0 + s * 8);
            cp16(bS[buf] + (uint32_t)((r0 * APAD + s * 8) * 2),
                 Bbase + (size_t)r0 * KK + bk0 + s * 8);
        }
        CP_COMMIT();
    };

    load_chunk(0, 0);

    for (int c = 0; c < nchunks; c++) {
        int buf = c & 1;
        if (c + 1 < nchunks) {
            load_chunk(c + 1, buf ^ 1);
            CP_WAIT(1);
        } else {
            CP_WAIT(0);
        }
        __syncthreads();

#pragma unroll
        for (int ks = 0; ks < 2; ks++) {
            uint32_t afr[4][4];
#pragma unroll
            for (int mi = 0; mi < 4; mi++)
                ldmx4(afr[mi], aS[buf] + aOff + (uint32_t)(mi * 16 * APAD * 2 + ks * 32));
            uint32_t bfr[2][4];
#pragma unroll
            for (int g = 0; g < 2; g++)
                ldmx4(bfr[g], bS[buf] + bOff + (uint32_t)(g * 16 * APAD * 2 + ks * 32));
#pragma unroll
            for (int mi = 0; mi < 4; mi++)
#pragma unroll
                for (int ni = 0; ni < 4; ni++)
                    mma_bf16(acc[mi][ni], afr[mi], bfr[ni >> 1][(ni & 1) * 2],
                             bfr[ni >> 1][(ni & 1) * 2 + 1]);
        }
        __syncthreads();
    }

    const float* bias = (bn < 2) ? bl : br;
    float*       Cout = (bn < 2) ? g_xl : g_xr;
    const int cbase = (bn & 1) * 128;
#pragma unroll
    for (int mi = 0; mi < 4; mi++) {
        int mrow = bm * MT + wm + mi * 16 + (lane >> 2);
#pragma unroll
        for (int ni = 0; ni < 4; ni++) {
            int col = cbase + wn + ni * 8 + (lane & 3) * 2;
            float b0 = bias[col], b1 = bias[col + 1];
            if (mrow < N_NODES) {
                float2 o = make_float2(acc[mi][ni][0] + b0, acc[mi][ni][1] + b1);
                *(float2*)&Cout[(size_t)mrow * 256 + col] = o;
            }
            if (mrow + 8 < N_NODES) {
                float2 o = make_float2(acc[mi][ni][2] + b0, acc[mi][ni][3] + b1);
                *(float2*)&Cout[(size_t)(mrow + 8) * 256 + col] = o;
            }
        }
    }
}

// ---------------- fused GATv2 edge kernel (one block per dst node) ---------------
__global__ __launch_bounds__(128)
void k_gat_edge(const float* __restrict__ We,
                const float* __restrict__ att,
                const float* __restrict__ bias,
                const float* __restrict__ eattr)
{
    int d = blockIdx.x;
    int t = threadIdx.x;
    int lane = t & 31;

    ull we2[32];
#pragma unroll
    for (int k = 0; k < 32; k++) {
        float2 w = *(const float2*)&We[k * 256 + 2 * t];
        we2[k] = pack2(w.x, w.y);
    }
    float2 xr2  = *(const float2*)&g_xr[(size_t)d * 256 + 2 * t];
    float2 att2 = *(const float2*)&att[2 * t];

    int e0  = g_rowptr[d];
    int e1  = g_rowptr[d + 1];
    int deg = e1 - e0;

    __shared__ __align__(16) ull ea_s[CHK_E][32];
    __shared__ int src_s[CHK_E];

    float m_run = -1e30f, s_run = 0.f;
    float accx = 0.f, accy = 0.f;

    for (int base = 0; base < deg; base += CHK_E) {
        int cnt = min(CHK_E, deg - base);
        if (t < cnt) src_s[t] = g_srcs[e0 + base + t];
        for (int j = (t >> 5); j < cnt; j += 4) {
            int eid = g_eidx[e0 + base + j];
            float v = eattr[(size_t)eid * 32 + lane];
            ea_s[j][lane] = pack2(v, v);
        }
        __syncthreads();

        int j = 0;
        for (; j + 1 < cnt; j += 2) {
            int sA = src_s[j], sB = src_s[j + 1];
            float2 xlA = *(const float2*)&g_xl[(size_t)sA * 256 + 2 * t];
            float2 xlB = *(const float2*)&g_xl[(size_t)sB * 256 + 2 * t];

            ull a0 = 0ull, a1 = 0ull, b0 = 0ull, b1 = 0ull;
#pragma unroll
            for (int k = 0; k < 32; k += 2) {
                ulonglong2 eA = *(const ulonglong2*)&ea_s[j][k];
                ulonglong2 eB = *(const ulonglong2*)&ea_s[j + 1][k];
                a0 = fma2(eA.x, we2[k],     a0);
                a1 = fma2(eA.y, we2[k + 1], a1);
                b0 = fma2(eB.x, we2[k],     b0);
                b1 = fma2(eB.y, we2[k + 1], b1);
            }
            float fax, fay, fbx, fby, gax, gay, gbx, gby;
            unpack2(a0, fax, fay); unpack2(a1, gax, gay);
            unpack2(b0, fbx, fby); unpack2(b1, gbx, gby);

            float vAx = xlA.x + xr2.x + fax + gax;
            float vAy = xlA.y + xr2.y + fay + gay;
            float vBx = xlB.x + xr2.x + fbx + gbx;
            float vBy = xlB.y + xr2.y + fby + gby;
            vAx = vAx > 0.f ? vAx : 0.2f * vAx;
            vAy = vAy > 0.f ? vAy : 0.2f * vAy;
            vBx = vBx > 0.f ? vBx : 0.2f * vBx;
            vBy = vBy > 0.f ? vBy : 0.2f * vBy;

            float pA = vAx * att2.x + vAy * att2.y;
            float pB = vBx * att2.x + vBy * att2.y;
#pragma unroll
            for (int off = 16; off; off >>= 1) {
                pA += __shfl_xor_sync(0xffffffffu, pA, off);
                pB += __shfl_xor_sync(0xffffffffu, pB, off);
            }

            float mnew  = fmaxf(m_run, fmaxf(pA, pB));
            float scale = __expf(m_run - mnew);
            float wA    = __expf(pA - mnew);
            float wB    = __expf(pB - mnew);
            s_run = s_run * scale + wA + wB;
            accx  = accx * scale + wA * xlA.x + wB * xlB.x;
            accy  = accy * scale + wA * xlA.y + wB * xlB.y;
            m_run = mnew;
        }
        if (j < cnt) {
            int sA = src_s[j];
            float2 xlA = *(const float2*)&g_xl[(size_t)sA * 256 + 2 * t];
            ull a0 = 0ull, a1 = 0ull;
#pragma unroll
            for (int k = 0; k < 32; k += 2) {
                ulonglong2 eA = *(const ulonglong2*)&ea_s[j][k];
                a0 = fma2(eA.x, we2[k],     a0);
                a1 = fma2(eA.y, we2[k + 1], a1);
            }
            float fax, fay, gax, gay;
            unpack2(a0, fax, fay); unpack2(a1, gax, gay);
            float vAx = xlA.x + xr2.x + fax + gax;
            float vAy = xlA.y + xr2.y + fay + gay;
            vAx = vAx > 0.f ? vAx : 0.2f * vAx;
            vAy = vAy > 0.f ? vAy : 0.2f * vAy;
            float pA = vAx * att2.x + vAy * att2.y;
#pragma unroll
            for (int off = 16; off; off >>= 1)
                pA += __shfl_xor_sync(0xffffffffu, pA, off);
            float mnew  = fmaxf(m_run, pA);
            float scale = __expf(m_run - mnew);
            float wA    = __expf(pA - mnew);
            s_run = s_run * scale + wA;
            accx  = accx * scale + wA * xlA.x;
            accy  = accy * scale + wA * xlA.y;
            m_run = mnew;
        }
        __syncthreads();
    }

    float inv = (deg > 0) ? (1.f / s_run) : 0.f;
    float ox = accx * inv + bias[2 * t];
    float oy = accy * inv + bias[2 * t + 1];
    ox = fmaxf(ox, 0.f);
    oy = fmaxf(oy, 0.f);
    *(float2*)&g_h[(size_t)d * 256 + 2 * t] = make_float2(ox, oy);
}

// ---------------- output projection ------------------------------------------------
__global__ __launch_bounds__(256)
void k_out(const float* __restrict__ Wout, const float* __restrict__ bout,
           float* __restrict__ y)
{
    int warp = (blockIdx.x * blockDim.x + threadIdx.x) >> 5;
    int lane = threadIdx.x & 31;
    if (warp >= N_NODES) return;
    const float* h = &g_h[(size_t)warp * 256];
    float s = 0.f;
#pragma unroll
    for (int i = 0; i < 8; i++)
        s += h[lane + 32 * i] * Wout[lane + 32 * i];
#pragma unroll
    for (int off = 16; off; off >>= 1)
        s += __shfl_xor_sync(0xffffffffu, s, off);
    if (lane == 0) y[warp] = s + bout[0];
}

// ---------------- launch -------------------------------------------------------------
extern "C" void kernel_launch(void* const* d_in, const int* in_sizes, int n_in,
                              void* d_out, int out_size)
{
    const float* x     = (const float*)d_in[0];
    const void*  ei    = d_in[1];
    const float* eattr = (const float*)d_in[2];
    const float* Wl0   = (const float*)d_in[3];
    const float* bl0   = (const float*)d_in[4];
    const float* Wr0   = (const float*)d_in[5];
    const float* br0   = (const float*)d_in[6];
    const float* We0   = (const float*)d_in[7];
    const float* att0  = (const float*)d_in[8];
    const float* bias0 = (const float*)d_in[9];
    const float* Wl1   = (const float*)d_in[10];
    const float* bl1   = (const float*)d_in[11];
    const float* Wr1   = (const float*)d_in[12];
    const float* br1   = (const float*)d_in[13];
    const float* We1   = (const float*)d_in[14];
    const float* att1  = (const float*)d_in[15];
    const float* bias1 = (const float*)d_in[16];
    const float* Wout  = (const float*)d_in[17];
    const float* bout  = (const float*)d_in[18];
    float* y = (float*)d_out;

    dim3 gmma(M_TILES, 4);

    // launch order arranged so k_mma (layer 0) is the 4th launch -> ncu profiles it
    k_detect <<<1, 32>>>((const int*)ei);            // 1
    k_cvt_w  <<<64, 256>>>(Wl0, Wr0, 512, 9);        // 2
    k_cvt_a  <<<512, 256>>>(x, 512, 9);              // 3
    k_mma    <<<gmma, 256>>>(1024, 1536, bl0, br0);  // 4  <-- profiled

    // CSR build (independent of GEMM)
    k_prep   <<<512, 256>>>(ei);
    k_hist   <<<512, 256>>>();
    k_scanA  <<<8, 256>>>();
    k_scanB  <<<1, 256>>>();
    k_scanC  <<<8, 256>>>();
    k_scatter<<<512, 256>>>();

    // layer 0 edge stage
    k_gat_edge<<<N_NODES, 128>>>(We0, att0, bias0, eattr);

    // layer 1
    k_cvt_w<<<64, 256>>>(Wl1, Wr1, 256, 8);
    k_cvt_a<<<512, 256>>>(nullptr, 256, 8);
    k_mma<<<gmma, 256>>>(512, 768, bl1, br1);
    k_gat_edge<<<N_NODES, 128>>>(We1, att1, bias1, eattr);

    // output projection
    k_out<<<(N_NODES * 32 + 255) / 256, 256>>>(Wout, bout, y);
}

// round 6
// speedup vs baseline: 1.6581x; 1.1292x over previous
#include <cuda_runtime.h>
#include <cuda_bf16.h>
#include <cstdint>

#define N_NODES 50000
#define N_EDGES 800000
#define IN_F    512
#define F       256

#define MT 128
#define NT 128
#define KC 32                  // bf16 elems per k-chunk (node GEMM)
#define M_TILES 391            // ceil(50000/128)
#define M_PAD   (M_TILES*128)  // 50048
#define APAD    40             // node-GEMM smem row stride (elems)

#define GDST 8                 // dst nodes per k_gat block
#define KP   104               // k_gat smem row stride (elems), 208B
#define SM_WE 0
#define SM_EA 53248            // 256*208
#define SM_SRC 56576           // + 16*208 = 3328 for ea
#define SM_TOT 56704

typedef unsigned long long ull;

// ---------------- scratch (device globals) -----------------------------------
__device__ int   g_is64;
__device__ int   g_src[N_EDGES];
__device__ int   g_dst[N_EDGES];
__device__ int   g_deg[N_NODES];
__device__ int   g_rowptr[N_NODES + 1];
__device__ int   g_cursor[N_NODES];
__device__ int   g_eidx[N_EDGES];
__device__ int   g_srcs[N_EDGES];
__device__ float g_xl[(size_t)N_NODES * F];
__device__ float g_xr[(size_t)N_NODES * F];
__device__ float g_h [(size_t)N_NODES * F];
__device__ __align__(16) __nv_bfloat16 g_abf[(size_t)M_PAD * 1024];   // A''=[hi|lo]
__device__ __align__(16) __nv_bfloat16 g_bbf[(size_t)512 * 1536];     // B''=[hi|hi|lo]
__device__ __align__(16) __nv_bfloat16 g_ebf2[(size_t)N_EDGES * 64];  // edge_attr [hi|lo], CSR order
__device__ __align__(16) __nv_bfloat16 g_bbe[256 * 96];               // We'' [n][hi|hi|lo]
#define SCAN_T 2048
__device__ int   g_tsum[SCAN_T];

// ---------------- helpers ------------------------------------------------------
__device__ __forceinline__ uint32_t smem_u32(const void* p) {
    uint32_t a;
    asm("{ .reg .u64 t; cvta.to.shared.u64 t, %1; cvt.u32.u64 %0, t; }"
        : "=r"(a) : "l"(p));
    return a;
}
__device__ __forceinline__ void cp16(uint32_t dst, const void* src) {
    asm volatile("cp.async.cg.shared.global [%0], [%1], 16;" :: "r"(dst), "l"(src));
}
#define CP_COMMIT() asm volatile("cp.async.commit_group;" ::: "memory")
#define CP_WAIT(n)  asm volatile("cp.async.wait_group %0;" :: "n"(n) : "memory")

__device__ __forceinline__ void ldmx4(uint32_t* r, uint32_t addr) {
    asm volatile("ldmatrix.sync.aligned.m8n8.x4.shared.b16 {%0,%1,%2,%3}, [%4];"
                 : "=r"(r[0]), "=r"(r[1]), "=r"(r[2]), "=r"(r[3]) : "r"(addr));
}
__device__ __forceinline__ void mma_bf16(float* c, const uint32_t* a, uint32_t b0, uint32_t b1) {
    asm volatile(
        "mma.sync.aligned.m16n8k16.row.col.f32.bf16.bf16.f32 "
        "{%0,%1,%2,%3}, {%4,%5,%6,%7}, {%8,%9}, {%0,%1,%2,%3};"
        : "+f"(c[0]), "+f"(c[1]), "+f"(c[2]), "+f"(c[3])
        : "r"(a[0]), "r"(a[1]), "r"(a[2]), "r"(a[3]), "r"(b0), "r"(b1));
}
__device__ __forceinline__ ull pack4bf(float a, float b, float c, float d) {
    ull r = (ull)__bfloat16_as_ushort(__float2bfloat16(a))
          | ((ull)__bfloat16_as_ushort(__float2bfloat16(b)) << 16)
          | ((ull)__bfloat16_as_ushort(__float2bfloat16(c)) << 32)
          | ((ull)__bfloat16_as_ushort(__float2bfloat16(d)) << 48);
    return r;
}

// ---------------- edge_index dtype detection + CSR build ------------------------
__global__ void k_detect(const int* ei32) {
    if (threadIdx.x == 0) {
        int is64 = 1;
        for (int i = 0; i < 32; i++)
            if (ei32[2 * i + 1] != 0) { is64 = 0; break; }
        g_is64 = is64;
    }
}
__global__ void k_prep(const void* ei) {
    const int is64 = g_is64;
    const int*       ei32 = (const int*)ei;
    const long long* ei64 = (const long long*)ei;
    int stride = gridDim.x * blockDim.x;
    for (int e = blockIdx.x * blockDim.x + threadIdx.x; e < N_EDGES; e += stride) {
        int s, d;
        if (is64) { s = (int)ei64[e]; d = (int)ei64[N_EDGES + e]; }
        else      { s = ei32[e];      d = ei32[N_EDGES + e]; }
        s = min(max(s, 0), N_NODES - 1);
        d = min(max(d, 0), N_NODES - 1);
        g_src[e] = s; g_dst[e] = d;
    }
    for (int i = blockIdx.x * blockDim.x + threadIdx.x; i < N_NODES; i += stride)
        g_deg[i] = 0;
}
__global__ void k_hist() {
    int stride = gridDim.x * blockDim.x;
    for (int e = blockIdx.x * blockDim.x + threadIdx.x; e < N_EDGES; e += stride)
        atomicAdd(&g_deg[g_dst[e]], 1);
}
__global__ void k_scanA() {
    int t = blockIdx.x * blockDim.x + threadIdx.x;
    int st = t * 25, en = min(st + 25, N_NODES);
    int s = 0;
    for (int i = st; i < en; i++) s += g_deg[i];
    g_tsum[t] = s;
}
__global__ void k_scanB() {
    __shared__ int sh[256];
    int t = threadIdx.x;
    int v[8]; int s = 0;
#pragma unroll
    for (int j = 0; j < 8; j++) v[j] = g_tsum[t * 8 + j];
#pragma unroll
    for (int j = 0; j < 8; j++) { int tmp = v[j]; v[j] = s; s += tmp; }
    sh[t] = s;
    __syncthreads();
    for (int off = 1; off < 256; off <<= 1) {
        int x = (t >= off) ? sh[t - off] : 0;
        __syncthreads();
        sh[t] += x;
        __syncthreads();
    }
    int base = (t == 0) ? 0 : sh[t - 1];
#pragma unroll
    for (int j = 0; j < 8; j++) g_tsum[t * 8 + j] = base + v[j];
}
__global__ void k_scanC() {
    int t = blockIdx.x * blockDim.x + threadIdx.x;
    int st = t * 25, en = min(st + 25, N_NODES);
    int run = g_tsum[t];
    for (int i = st; i < en; i++) {
        g_rowptr[i] = run;
        g_cursor[i] = run;
        run += g_deg[i];
    }
    if (t == 0) g_rowptr[N_NODES] = N_EDGES;
}
__global__ void k_scatter() {
    int stride = gridDim.x * blockDim.x;
    for (int e = blockIdx.x * blockDim.x + threadIdx.x; e < N_EDGES; e += stride) {
        int s = g_src[e];
        int p = atomicAdd(&g_cursor[g_dst[e]], 1);
        g_eidx[p] = e;
        g_srcs[p] = s;
    }
}

// ---------------- bf16 split conversions -----------------------------------------
__global__ void k_cvt_a(const float* A_in, int K, int kshift) {
    const float* A = A_in ? A_in : g_h;
    size_t total = (size_t)N_NODES * K;
    size_t stride = (size_t)gridDim.x * blockDim.x;
    for (size_t i = blockIdx.x * (size_t)blockDim.x + threadIdx.x; i < total; i += stride) {
        size_t row = i >> kshift;
        int k = (int)(i & (K - 1));
        float a = A[i];
        __nv_bfloat16 hi = __float2bfloat16(a);
        __nv_bfloat16 lo = __float2bfloat16(a - __bfloat162float(hi));
        size_t base = row * (size_t)(2 * K);
        g_abf[base + k]     = hi;
        g_abf[base + K + k] = lo;
    }
}
__global__ void k_cvt_w(const float* Wl, const float* Wr, int K, int kshift) {
    int KK = 3 * K;
    int total = 512 * K;
    int stride = gridDim.x * blockDim.x;
    for (int i = blockIdx.x * blockDim.x + threadIdx.x; i < total; i += stride) {
        int n = i >> kshift;
        int k = i & (K - 1);
        float w = (n < 256) ? Wl[(size_t)k * 256 + n] : Wr[(size_t)k * 256 + (n - 256)];
        __nv_bfloat16 hi = __float2bfloat16(w);
        __nv_bfloat16 lo = __float2bfloat16(w - __bfloat162float(hi));
        size_t base = (size_t)n * KK;
        g_bbf[base + k]         = hi;
        g_bbf[base + K + k]     = hi;
        g_bbf[base + 2 * K + k] = lo;
    }
}
// edge_attr -> g_ebf2 [p][hi(0:32)|lo(32:64)], CSR-permuted
__global__ void k_cvt_e(const float* __restrict__ eattr) {
    int i = blockIdx.x * blockDim.x + threadIdx.x;
    if (i >= N_EDGES * 8) return;
    int p = i >> 3, kq = (i & 7) * 4;
    int e = g_eidx[p];
    float4 v = *(const float4*)&eattr[(size_t)e * 32 + kq];
    float hx = __bfloat162float(__float2bfloat16(v.x));
    float hy = __bfloat162float(__float2bfloat16(v.y));
    float hz = __bfloat162float(__float2bfloat16(v.z));
    float hw = __bfloat162float(__float2bfloat16(v.w));
    *(ull*)&g_ebf2[(size_t)p * 64 + kq]      = pack4bf(v.x, v.y, v.z, v.w);
    *(ull*)&g_ebf2[(size_t)p * 64 + 32 + kq] = pack4bf(v.x - hx, v.y - hy, v.z - hz, v.w - hw);
}
// We [32][256] -> g_bbe [n][hi(0:32)|hi(32:64)|lo(64:96)]
__global__ void k_cvt_we(const float* __restrict__ We) {
    int i = blockIdx.x * blockDim.x + threadIdx.x;
    if (i >= 2048) return;
    int n = i >> 3, kq = (i & 7) * 4;
    float w0 = We[(kq + 0) * 256 + n];
    float w1 = We[(kq + 1) * 256 + n];
    float w2 = We[(kq + 2) * 256 + n];
    float w3 = We[(kq + 3) * 256 + n];
    float h0 = __bfloat162float(__float2bfloat16(w0));
    float h1 = __bfloat162float(__float2bfloat16(w1));
    float h2 = __bfloat162float(__float2bfloat16(w2));
    float h3 = __bfloat162float(__float2bfloat16(w3));
    ull hi = pack4bf(w0, w1, w2, w3);
    ull lo = pack4bf(w0 - h0, w1 - h1, w2 - h2, w3 - h3);
    *(ull*)&g_bbe[n * 96 + kq]      = hi;
    *(ull*)&g_bbe[n * 96 + 32 + kq] = hi;
    *(ull*)&g_bbe[n * 96 + 64 + kq] = lo;
}

// ---------------- mma.sync GEMM: [xl|xr] = A''@B''^T + bias -----------------------
__global__ __launch_bounds__(256)
void k_mma(int KA /*2K*/, int KK /*3K*/,
           const float* __restrict__ bl, const float* __restrict__ br)
{
    __shared__ __align__(128) __nv_bfloat16 smA[2][128 * APAD];
    __shared__ __align__(128) __nv_bfloat16 smB[2][128 * APAD];

    const int tid  = threadIdx.x;
    const int wid  = tid >> 5, lane = tid & 31;
    const int wm   = (wid & 1) * 64;
    const int wn   = (wid >> 1) * 32;
    const int bm   = blockIdx.x, bn = blockIdx.y;

    const __nv_bfloat16* Abase = g_abf + (size_t)bm * MT * KA;
    const __nv_bfloat16* Bbase = g_bbf + (size_t)bn * NT * KK;

    const int nchunks = KK / KC;
    const int n2      = KA / KC;

    const int r0 = tid >> 1, s0 = (tid & 1) * 2;
    uint32_t aS[2], bS[2];
    aS[0] = smem_u32(&smA[0][0]); aS[1] = smem_u32(&smA[1][0]);
    bS[0] = smem_u32(&smB[0][0]); bS[1] = smem_u32(&smB[1][0]);

    const uint32_t aOff = (uint32_t)(((wm + (lane & 15)) * APAD + (lane >> 4) * 8) * 2);
    const uint32_t bOff = (uint32_t)(((wn + (lane & 7) + ((lane >> 4) & 1) * 8) * APAD
                                      + ((lane >> 3) & 1) * 8) * 2);

    float acc[4][4][4];
#pragma unroll
    for (int i = 0; i < 4; i++)
#pragma unroll
        for (int j = 0; j < 4; j++)
#pragma unroll
            for (int q = 0; q < 4; q++) acc[i][j][q] = 0.f;

    auto load_chunk = [&](int c, int buf) {
        int ak0 = ((c < n2) ? c : (c - n2)) * KC;
        int bk0 = c * KC;
#pragma unroll
        for (int i = 0; i < 2; i++) {
            int s = s0 + i;
            cp16(aS[buf] + (uint32_t)((r0 * APAD + s * 8) * 2),
                 Abase + (size_t)r0 * KA + ak0 + s * 8);
            cp16(bS[buf] + (uint32_t)((r0 * APAD + s * 8) * 2),
                 Bbase + (size_t)r0 * KK + bk0 + s * 8);
        }
        CP_COMMIT();
    };

    load_chunk(0, 0);

    for (int c = 0; c < nchunks; c++) {
        int buf = c & 1;
        if (c + 1 < nchunks) {
            load_chunk(c + 1, buf ^ 1);
            CP_WAIT(1);
        } else {
            CP_WAIT(0);
        }
        __syncthreads();

#pragma unroll
        for (int ks = 0; ks < 2; ks++) {
            uint32_t afr[4][4];
#pragma unroll
            for (int mi = 0; mi < 4; mi++)
                ldmx4(afr[mi], aS[buf] + aOff + (uint32_t)(mi * 16 * APAD * 2 + ks * 32));
            uint32_t bfr[2][4];
#pragma unroll
            for (int g = 0; g < 2; g++)
                ldmx4(bfr[g], bS[buf] + bOff + (uint32_t)(g * 16 * APAD * 2 + ks * 32));
#pragma unroll
            for (int mi = 0; mi < 4; mi++)
#pragma unroll
                for (int ni = 0; ni < 4; ni++)
                    mma_bf16(acc[mi][ni], afr[mi], bfr[ni >> 1][(ni & 1) * 2],
                             bfr[ni >> 1][(ni & 1) * 2 + 1]);
        }
        __syncthreads();
    }

    const float* bias = (bn < 2) ? bl : br;
    float*       Cout = (bn < 2) ? g_xl : g_xr;
    const int cbase = (bn & 1) * 128;
#pragma unroll
    for (int mi = 0; mi < 4; mi++) {
        int mrow = bm * MT + wm + mi * 16 + (lane >> 2);
#pragma unroll
        for (int ni = 0; ni < 4; ni++) {
            int col = cbase + wn + ni * 8 + (lane & 3) * 2;
            float b0 = bias[col], b1 = bias[col + 1];
            if (mrow < N_NODES) {
                float2 o = make_float2(acc[mi][ni][0] + b0, acc[mi][ni][1] + b1);
                *(float2*)&Cout[(size_t)mrow * 256 + col] = o;
            }
            if (mrow + 8 < N_NODES) {
                float2 o = make_float2(acc[mi][ni][2] + b0, acc[mi][ni][3] + b1);
                *(float2*)&Cout[(size_t)(mrow + 8) * 256 + col] = o;
            }
        }
    }
}

// ---------------- fused GATv2 edge kernel: mma-based ea, per-head softmax ----------
// Block = 8 dst nodes, warp w = head w (channels [64w, 64w+64)).
__global__ __launch_bounds__(128)
void k_gat(const float* __restrict__ att, const float* __restrict__ bias)
{
    extern __shared__ __align__(16) char sm[];
    const uint32_t sWeU = smem_u32(sm) + SM_WE;
    const uint32_t sEaU = smem_u32(sm) + SM_EA;
    int* src_s = (int*)(sm + SM_SRC);

    const int tid = threadIdx.x, w = tid >> 5, lane = tid & 31;
    const int cl0 = (lane & 3) * 2;
    const int rA  = lane >> 2;

    // stage We'' (256 rows x 96 elems -> smem rows of 208B)
#pragma unroll
    for (int i = 0; i < 24; i++) {
        int c = tid + i * 128;
        int n = c / 12, seg = c % 12;
        cp16(sWeU + (uint32_t)(n * 208 + seg * 16), g_bbe + n * 96 + seg * 8);
    }
    CP_COMMIT();

    float2 att2[8], bias2[8];
#pragma unroll
    for (int i = 0; i < 8; i++) {
        int col = w * 64 + i * 8 + cl0;
        att2[i]  = *(const float2*)&att[col];
        bias2[i] = *(const float2*)&bias[col];
    }
    const uint32_t aOff = (uint32_t)(((lane & 15) * KP + (lane >> 4) * 8) * 2);
    const uint32_t bOff = (uint32_t)(((w * 64 + (lane & 7) + ((lane >> 4) & 1) * 8) * KP
                                      + ((lane >> 3) & 1) * 8) * 2);

    for (int dd = 0; dd < GDST; dd++) {
        int d = blockIdx.x * GDST + dd;
        if (d >= N_NODES) break;
        int e0 = g_rowptr[d];
        int deg = g_rowptr[d + 1] - e0;

        float2 xr2[8];
#pragma unroll
        for (int i = 0; i < 8; i++)
            xr2[i] = *(const float2*)&g_xr[(size_t)d * 256 + w * 64 + i * 8 + cl0];

        float m_run = -1e30f, s_run = 0.f;      // per-warp = per-head state
        float2 accr[8];
#pragma unroll
        for (int i = 0; i < 8; i++) accr[i] = make_float2(0.f, 0.f);

        for (int base = 0; base < deg; base += 16) {
            int cnt = min(16, deg - base);
            int p0 = e0 + base;
            __syncthreads();   // protect sEa/src_s from prior-iteration readers

            if (tid < 16) src_s[tid] = (tid < cnt) ? g_srcs[p0 + tid] : 0;
#pragma unroll
            for (int i = 0; i < 2; i++) {
                int c = tid + i * 128;
                if (c < 192) {
                    int row = c / 12, seg = c % 12;
                    uint32_t dst = sEaU + (uint32_t)(row * 208 + seg * 16);
                    if (row < cnt) {
                        int off = (seg < 4) ? seg * 8 : (seg < 8) ? 32 + (seg - 4) * 8 : (seg - 8) * 8;
                        cp16(dst, g_ebf2 + (size_t)(p0 + row) * 64 + off);
                    } else {
                        asm volatile("st.shared.v4.b32 [%0], {%1,%1,%1,%1};"
                                     :: "r"(dst), "r"(0) : "memory");
                    }
                }
            }
            CP_COMMIT(); CP_WAIT(0);
            __syncthreads();

            int sA = src_s[rA], sB = src_s[rA + 8];
            float2 xlA[8], xlB[8];
#pragma unroll
            for (int i = 0; i < 8; i++) {
                xlA[i] = __ldg((const float2*)&g_xl[(size_t)sA * 256 + w * 64 + i * 8 + cl0]);
                xlB[i] = __ldg((const float2*)&g_xl[(size_t)sB * 256 + w * 64 + i * 8 + cl0]);
            }

            float acc[8][4];
#pragma unroll
            for (int i = 0; i < 8; i++) { acc[i][0] = acc[i][1] = acc[i][2] = acc[i][3] = 0.f; }
#pragma unroll
            for (int ks = 0; ks < 6; ks++) {
                uint32_t afr[4];
                ldmx4(afr, sEaU + aOff + (uint32_t)(ks * 32));
#pragma unroll
                for (int g2 = 0; g2 < 4; g2++) {
                    uint32_t bfr[4];
                    ldmx4(bfr, sWeU + bOff + (uint32_t)(g2 * 16 * 208 + ks * 32));
                    mma_bf16(acc[2 * g2],     afr, bfr[0], bfr[1]);
                    mma_bf16(acc[2 * g2 + 1], afr, bfr[2], bfr[3]);
                }
            }

            // per-head logits (warp covers all 64 channels of head w)
            float pA = 0.f, pB = 0.f;
#pragma unroll
            for (int i = 0; i < 8; i++) {
                float vx = acc[i][0] + xlA[i].x + xr2[i].x;
                float vy = acc[i][1] + xlA[i].y + xr2[i].y;
                vx = vx > 0.f ? vx : 0.2f * vx;
                vy = vy > 0.f ? vy : 0.2f * vy;
                pA += vx * att2[i].x + vy * att2[i].y;
                float ux = acc[i][2] + xlB[i].x + xr2[i].x;
                float uy = acc[i][3] + xlB[i].y + xr2[i].y;
                ux = ux > 0.f ? ux : 0.2f * ux;
                uy = uy > 0.f ? uy : 0.2f * uy;
                pB += ux * att2[i].x + uy * att2[i].y;
            }
            // quad-reduce: lanes in a quad hold the full head-w logit for edges rA / rA+8
            pA += __shfl_xor_sync(0xffffffffu, pA, 1);
            pA += __shfl_xor_sync(0xffffffffu, pA, 2);
            pB += __shfl_xor_sync(0xffffffffu, pB, 1);
            pB += __shfl_xor_sync(0xffffffffu, pB, 2);

            float lA = (rA     < cnt) ? pA : -1e30f;
            float lB = (rA + 8 < cnt) ? pB : -1e30f;
            float mc = fmaxf(lA, lB);
#pragma unroll
            for (int o = 4; o <= 16; o <<= 1)
                mc = fmaxf(mc, __shfl_xor_sync(0xffffffffu, mc, o));
            float mnew = fmaxf(m_run, mc);
            float scl  = __expf(m_run - mnew);
            float wA   = __expf(lA - mnew);
            float wB   = __expf(lB - mnew);
            float sch  = wA + wB;
#pragma unroll
            for (int o = 4; o <= 16; o <<= 1)
                sch += __shfl_xor_sync(0xffffffffu, sch, o);
            s_run = s_run * scl + sch;
#pragma unroll
            for (int i = 0; i < 8; i++) {
                float cx = wA * xlA[i].x + wB * xlB[i].x;
                float cy = wA * xlA[i].y + wB * xlB[i].y;
#pragma unroll
                for (int o = 4; o <= 16; o <<= 1) {
                    cx += __shfl_xor_sync(0xffffffffu, cx, o);
                    cy += __shfl_xor_sync(0xffffffffu, cy, o);
                }
                accr[i].x = accr[i].x * scl + cx;
                accr[i].y = accr[i].y * scl + cy;
            }
            m_run = mnew;
        }

        if (rA == 0) {
            float inv = (deg > 0) ? (1.f / s_run) : 0.f;
#pragma unroll
            for (int i = 0; i < 8; i++) {
                float ox = fmaxf(accr[i].x * inv + bias2[i].x, 0.f);
                float oy = fmaxf(accr[i].y * inv + bias2[i].y, 0.f);
                *(float2*)&g_h[(size_t)d * 256 + w * 64 + i * 8 + cl0] = make_float2(ox, oy);
            }
        }
    }
}

// ---------------- output projection -------------------------------------------------
__global__ __launch_bounds__(256)
void k_out(const float* __restrict__ Wout, const float* __restrict__ bout,
           float* __restrict__ y)
{
    int warp = (blockIdx.x * blockDim.x + threadIdx.x) >> 5;
    int lane = threadIdx.x & 31;
    if (warp >= N_NODES) return;
    const float* h = &g_h[(size_t)warp * 256];
    float s = 0.f;
#pragma unroll
    for (int i = 0; i < 8; i++)
        s += h[lane + 32 * i] * Wout[lane + 32 * i];
#pragma unroll
    for (int off = 16; off; off >>= 1)
        s += __shfl_xor_sync(0xffffffffu, s, off);
    if (lane == 0) y[warp] = s + bout[0];
}

// ---------------- launch --------------------------------------------------------------
extern "C" void kernel_launch(void* const* d_in, const int* in_sizes, int n_in,
                              void* d_out, int out_size)
{
    const float* x     = (const float*)d_in[0];
    const void*  ei    = d_in[1];
    const float* eattr = (const float*)d_in[2];
    const float* Wl0   = (const float*)d_in[3];
    const float* bl0   = (const float*)d_in[4];
    const float* Wr0   = (const float*)d_in[5];
    const float* br0   = (const float*)d_in[6];
    const float* We0   = (const float*)d_in[7];
    const float* att0  = (const float*)d_in[8];
    const float* bias0 = (const float*)d_in[9];
    const float* Wl1   = (const float*)d_in[10];
    const float* bl1   = (const float*)d_in[11];
    const float* Wr1   = (const float*)d_in[12];
    const float* br1   = (const float*)d_in[13];
    const float* We1   = (const float*)d_in[14];
    const float* att1  = (const float*)d_in[15];
    const float* bias1 = (const float*)d_in[16];
    const float* Wout  = (const float*)d_in[17];
    const float* bout  = (const float*)d_in[18];
    float* y = (float*)d_out;

    cudaFuncSetAttribute(k_gat, cudaFuncAttributeMaxDynamicSharedMemorySize, SM_TOT);

    dim3 gmma(M_TILES, 4);
    const int ggat = (N_NODES + GDST - 1) / GDST;

    // launch order keeps k_mma (layer 0) as the 4th launch -> profiled
    k_detect <<<1, 32>>>((const int*)ei);            // 1
    k_cvt_w  <<<64, 256>>>(Wl0, Wr0, 512, 9);        // 2
    k_cvt_a  <<<512, 256>>>(x, 512, 9);              // 3
    k_mma    <<<gmma, 256>>>(1024, 1536, bl0, br0);  // 4  <-- profiled

    // CSR build
    k_prep   <<<512, 256>>>(ei);
    k_hist   <<<512, 256>>>();
    k_scanA  <<<8, 256>>>();
    k_scanB  <<<1, 256>>>();
    k_scanC  <<<8, 256>>>();
    k_scatter<<<512, 256>>>();

    // edge_attr split (CSR order, shared by both layers) + We0
    k_cvt_e  <<<(N_EDGES * 8 + 255) / 256, 256>>>(eattr);
    k_cvt_we <<<8, 256>>>(We0);

    // layer 0 edge stage
    k_gat<<<ggat, 128, SM_TOT>>>(att0, bias0);

    // layer 1
    k_cvt_w<<<64, 256>>>(Wl1, Wr1, 256, 8);
    k_cvt_a<<<512, 256>>>(nullptr, 256, 8);
    k_mma<<<gmma, 256>>>(512, 768, bl1, br1);
    k_cvt_we<<<8, 256>>>(We1);
    k_gat<<<ggat, 128, SM_TOT>>>(att1, bias1);

    // output projection
    k_out<<<(N_NODES * 32 + 255) / 256, 256>>>(Wout, bout, y);
}